// round 17
// baseline (speedup 1.0000x reference)
#include <cuda_runtime.h>
#include <math.h>
#include <stdint.h>

// Problem constants (fixed shapes)
#define B_  16
#define C_  128
#define H_  64
#define W_  64
#define G_  4
#define CG_ 32
#define HW_ 4096      // H_*W_
#define HS_ 128
#define WS_ 128
#define BH_ 8         // batches per pipeline segment

// Scratch (static device globals; no runtime allocation)
__device__ uint32_t d_Wt[C_ * C_];         // Wt[k][n] = tf32(w_proj[n,k] * bn_scale[n])
__device__ float d_tb[C_];                 // folded bias
__device__ float d_p[B_ * G_ * HW_ * CG_]; // p in (b,g,pix,cg) layout, 33.5MB
__device__ float d_off[B_ * 8 * HW_];      // tanh offsets, NCHW (B,2G,H,W)
__device__ float d_part[4 * B_ * 8 * HW_]; // K2 k-split partial sums, 8MB

// ---- packed fp32x2 helpers ----
__device__ __forceinline__ float2 fma2(float2 a, float2 b, float2 c) {
    float2 d;
    asm("fma.rn.f32x2 %0, %1, %2, %3;"
        : "=l"(reinterpret_cast<unsigned long long&>(d))
        : "l"(reinterpret_cast<unsigned long long&>(a)),
          "l"(reinterpret_cast<unsigned long long&>(b)),
          "l"(reinterpret_cast<unsigned long long&>(c)));
    return d;
}
__device__ __forceinline__ float2 mul2(float2 a, float2 b) {
    float2 d;
    asm("mul.rn.f32x2 %0, %1, %2;"
        : "=l"(reinterpret_cast<unsigned long long&>(d))
        : "l"(reinterpret_cast<unsigned long long&>(a)),
          "l"(reinterpret_cast<unsigned long long&>(b)));
    return d;
}
__device__ __forceinline__ uint32_t to_tf32(float v) {
    uint32_t u;
    asm("cvt.rna.tf32.f32 %0, %1;" : "=r"(u) : "f"(v));
    return u;
}

// ---------------------------------------------------------------------------
// K0: fold BN into transposed weights (tf32-rounded) + folded bias
// ---------------------------------------------------------------------------
__global__ void k0_prep(const float* __restrict__ w_proj,
                        const float* __restrict__ gamma,
                        const float* __restrict__ beta,
                        const float* __restrict__ mean,
                        const float* __restrict__ var) {
    int idx = blockIdx.x * blockDim.x + threadIdx.x;
    if (idx >= C_ * C_) return;
    int k = idx >> 7;
    int n = idx & 127;
    float s = gamma[n] * rsqrtf(var[n] + 1e-5f);
    d_Wt[k * C_ + n] = to_tf32(w_proj[n * C_ + k] * s);
    if (idx < C_) {
        d_tb[idx] = beta[idx] - mean[idx] * (gamma[idx] * rsqrtf(var[idx] + 1e-5f));
    }
}

// ---------------------------------------------------------------------------
// K1: 1x1 conv as TF32 mma.sync GEMM, double-buffered 16-k panels.
//     Segment launch: grid (32, BH_), batch = b0 + blockIdx.y.
// ---------------------------------------------------------------------------
#define KP    16
#define SKSTR 136
__global__ __launch_bounds__(256) void k1_mma(const float* __restrict__ x, int b0) {
    __shared__ uint32_t As[2][KP * SKSTR];
    __shared__ uint32_t Bs[2][KP * SKSTR];
    __shared__ float sTb[128];

    int b = b0 + blockIdx.y;
    int pix0 = blockIdx.x * 128;
    int t = threadIdx.x;
    int wid = t >> 5;
    int lane = t & 31;
    int gid = lane >> 2;
    int tg = lane & 3;
    int mbase = (wid & 3) * 32;
    int nbase = (wid >> 2) * 64;

    if (t < 128) sTb[t] = d_tb[t];

    const float* xb = x + (size_t)b * C_ * HW_ + pix0;

    int fk[2], fc[2];
#pragma unroll
    for (int i = 0; i < 2; i++) {
        int s = t + i * 256;
        fk[i] = s >> 5;
        fc[i] = (s & 31) * 4;
    }

    float4 stg[2];

#define K1_STAGE_A(p) do { _Pragma("unroll") \
    for (int i = 0; i < 2; i++) \
        stg[i] = *(const float4*)&xb[(size_t)((p) * KP + fk[i]) * HW_ + fc[i]]; } while (0)

#define K1_COMMIT_A(p) do { uint32_t* Ad = As[(p) & 1]; _Pragma("unroll") \
    for (int i = 0; i < 2; i++) { uint32_t* d = Ad + fk[i] * SKSTR + fc[i]; \
        d[0] = to_tf32(stg[i].x); d[1] = to_tf32(stg[i].y); \
        d[2] = to_tf32(stg[i].z); d[3] = to_tf32(stg[i].w); } } while (0)

#define K1_FILL_B(p) do { \
    uint32_t sb = (uint32_t)__cvta_generic_to_shared(Bs[(p) & 1]); \
    _Pragma("unroll") for (int i = 0; i < 2; i++) { \
        uint32_t dst = sb + (uint32_t)(fk[i] * SKSTR + fc[i]) * 4u; \
        const uint32_t* src = d_Wt + ((p) * KP + fk[i]) * C_ + fc[i]; \
        asm volatile("cp.async.ca.shared.global [%0], [%1], 16;" :: "r"(dst), "l"(src)); } \
    asm volatile("cp.async.commit_group;"); } while (0)

    K1_STAGE_A(0);
    K1_FILL_B(0);
    K1_COMMIT_A(0);
    asm volatile("cp.async.wait_group 0;" ::: "memory");
    __syncthreads();

    float acc[2][8][4];
#pragma unroll
    for (int mt = 0; mt < 2; mt++)
#pragma unroll
        for (int nt = 0; nt < 8; nt++)
#pragma unroll
            for (int z = 0; z < 4; z++) acc[mt][nt][z] = 0.f;

#pragma unroll 1
    for (int p = 0; p < 8; p++) {
        if (p < 7) { K1_STAGE_A(p + 1); K1_FILL_B(p + 1); }

        const uint32_t* A = As[p & 1];
        const uint32_t* Bp = Bs[p & 1];

#pragma unroll
        for (int ks = 0; ks < 2; ks++) {
            int kk = ks * 8;
            uint32_t a[2][4];
#pragma unroll
            for (int mt = 0; mt < 2; mt++) {
                int m = mbase + mt * 16 + gid;
                const uint32_t* ap = A + (kk + tg) * SKSTR + m;
                a[mt][0] = ap[0];
                a[mt][1] = ap[8];
                a[mt][2] = ap[4 * SKSTR];
                a[mt][3] = ap[4 * SKSTR + 8];
            }
#pragma unroll
            for (int nt = 0; nt < 8; nt++) {
                int n = nbase + nt * 8 + gid;
                uint32_t b0r = Bp[(kk + tg) * SKSTR + n];
                uint32_t b1r = Bp[(kk + tg + 4) * SKSTR + n];
#pragma unroll
                for (int mt = 0; mt < 2; mt++) {
                    asm volatile(
                        "mma.sync.aligned.m16n8k8.row.col.f32.tf32.tf32.f32 "
                        "{%0,%1,%2,%3}, {%4,%5,%6,%7}, {%8,%9}, {%0,%1,%2,%3};"
                        : "+f"(acc[mt][nt][0]), "+f"(acc[mt][nt][1]),
                          "+f"(acc[mt][nt][2]), "+f"(acc[mt][nt][3])
                        : "r"(a[mt][0]), "r"(a[mt][1]), "r"(a[mt][2]), "r"(a[mt][3]),
                          "r"(b0r), "r"(b1r));
                }
            }
        }

        if (p < 7) {
            K1_COMMIT_A(p + 1);
            asm volatile("cp.async.wait_group 0;" ::: "memory");
        }
        __syncthreads();
    }

#pragma unroll
    for (int mt = 0; mt < 2; mt++) {
        int pixA = pix0 + mbase + mt * 16 + gid;
        int pixB = pixA + 8;
#pragma unroll
        for (int nt = 0; nt < 8; nt++) {
            int n = nbase + nt * 8 + 2 * tg;
            int g = n >> 5, cg = n & 31;
            float t0 = sTb[n], t1 = sTb[n + 1];
            float u;
            float2 vA, vB;
            u = acc[mt][nt][0] + t0; vA.x = u * (1.f / (1.f + __expf(-u)));
            u = acc[mt][nt][1] + t1; vA.y = u * (1.f / (1.f + __expf(-u)));
            u = acc[mt][nt][2] + t0; vB.x = u * (1.f / (1.f + __expf(-u)));
            u = acc[mt][nt][3] + t1; vB.y = u * (1.f / (1.f + __expf(-u)));
            float* base = d_p + ((size_t)(b * G_ + g) * HW_) * CG_ + cg;
            *(float2*)(base + (size_t)pixA * CG_) = vA;
            *(float2*)(base + (size_t)pixB * CG_) = vB;
        }
    }
}

// ---------------------------------------------------------------------------
// K2a: 3x3 conv partials, 32-channel k-slice, cp.async 4-deep pipeline.
//      Segment launch: grid (2, 4, BH_*4); z = (b-b0)*4 + split.
// ---------------------------------------------------------------------------
#define XSTR 35
__global__ __launch_bounds__(256, 4) void k2a_conv3(const float* __restrict__ x,
                                                    const float* __restrict__ w_off,
                                                    int b0) {
    __shared__ float ws[32 * 72];
    __shared__ float xbuf[4][18 * XSTR];

    int bz = blockIdx.z;
    int b = b0 + (bz >> 2);
    int split = bz & 3;
    int k_lo = split * 32;
    int h0 = blockIdx.y * 16;
    int w0 = blockIdx.x * 32;
    int tid = threadIdx.y * 16 + threadIdx.x;
    int tx = threadIdx.x;
    int ty = threadIdx.y;

    for (int idx = tid; idx < 32 * 9 * 8; idx += 256) {
        int kk = idx / 72;
        int r = idx - kk * 72;
        int t = r >> 3;
        int oc = r & 7;
        ws[idx] = w_off[oc * (C_ * 9) + (k_lo + kk) * 9 + t];
    }
    for (int i = tid; i < 4 * 18 * XSTR; i += 256) ((float*)xbuf)[i] = 0.f;

    const float* xb = x + (size_t)b * C_ * HW_ + (size_t)k_lo * HW_;

    uint32_t soff[3];
    int goff[3];
    bool sval[3];
    uint32_t sb0 = (uint32_t)__cvta_generic_to_shared(&xbuf[0][0]);
#pragma unroll
    for (int i = 0; i < 3; i++) {
        int idx = tid + i * 256;
        int r = idx / 34, cc = idx - r * 34;
        int h = h0 - 1 + r, w = w0 - 1 + cc;
        soff[i] = (uint32_t)(r * XSTR + cc) * 4u;
        goff[i] = h * W_ + w;
        sval[i] = (idx < 612) && (h >= 0) && (h < H_) && (w >= 0) && (w < W_);
    }

    __syncthreads();

#pragma unroll
    for (int kk = 0; kk < 3; kk++) {
        const float* src = xb + (size_t)kk * HW_;
        uint32_t base = sb0 + (uint32_t)kk * (18 * XSTR * 4);
#pragma unroll
        for (int i = 0; i < 3; i++)
            if (sval[i])
                asm volatile("cp.async.ca.shared.global [%0], [%1], 4;"
                             :: "r"(base + soff[i]), "l"(src + goff[i]));
        asm volatile("cp.async.commit_group;");
    }

    float2 acc0[4], acc1[4];
#pragma unroll
    for (int q = 0; q < 4; q++) { acc0[q] = make_float2(0.f, 0.f); acc1[q] = make_float2(0.f, 0.f); }

    for (int k = 0; k < 32; k++) {
        asm volatile("cp.async.wait_group 2;" ::: "memory");
        __syncthreads();

        if (k + 3 < 32) {
            const float* src = xb + (size_t)(k + 3) * HW_;
            uint32_t base = sb0 + (uint32_t)((k + 3) & 3) * (18 * XSTR * 4);
#pragma unroll
            for (int i = 0; i < 3; i++)
                if (sval[i])
                    asm volatile("cp.async.ca.shared.global [%0], [%1], 4;"
                                 :: "r"(base + soff[i]), "l"(src + goff[i]));
        }
        asm volatile("cp.async.commit_group;");

        const float* xtc = &xbuf[k & 3][0];
        float xv[3][4];
#pragma unroll
        for (int r = 0; r < 3; r++)
#pragma unroll
            for (int c = 0; c < 4; c++) xv[r][c] = xtc[(ty + r) * XSTR + 2 * tx + c];

        const float* wk = &ws[k * 72];
#pragma unroll
        for (int t = 0; t < 9; t++) {
            int dy = t / 3, dx = t - dy * 3;
            float2 wp[4];
            *(float4*)&wp[0] = *(const float4*)&wk[t * 8 + 0];
            *(float4*)&wp[2] = *(const float4*)&wk[t * 8 + 4];
            float2 xp0 = make_float2(xv[dy][dx], xv[dy][dx]);
            float2 xp1 = make_float2(xv[dy][dx + 1], xv[dy][dx + 1]);
#pragma unroll
            for (int q = 0; q < 4; q++) {
                acc0[q] = fma2(xp0, wp[q], acc0[q]);
                acc1[q] = fma2(xp1, wp[q], acc1[q]);
            }
        }
    }

    int y = h0 + ty;
    int xw = w0 + 2 * tx;
    float* pbase = d_part + (size_t)(split * B_ + b) * 8 * HW_;
#pragma unroll
    for (int q = 0; q < 4; q++) {
        float a0[2] = { acc0[q].x, acc0[q].y };
        float a1[2] = { acc1[q].x, acc1[q].y };
#pragma unroll
        for (int h = 0; h < 2; h++) {
            int oc = q * 2 + h;
            size_t base = (size_t)oc * HW_ + y * W_ + xw;
            pbase[base] = a0[h];
            pbase[base + 1] = a1[h];
        }
    }
}

// ---------------------------------------------------------------------------
// K2b: reduce 4 partials + bias + tanh -> d_off. Segment: BH_ batches.
// ---------------------------------------------------------------------------
__global__ void k2b_reduce(const float* __restrict__ b_off, int b0) {
    int i = blockIdx.x * blockDim.x + threadIdx.x;
    const int N4 = BH_ * 8 * HW_ / 4;
    if (i >= N4) return;
    int e = i * 4;
    int r = e & (8 * HW_ - 1);
    int b = b0 + e / (8 * HW_);
    int oc = r / HW_;

    const float4* p0 = (const float4*)(d_part + ((size_t)(0 * B_ + b) * 8) * HW_ + r);
    const float4* p1 = (const float4*)(d_part + ((size_t)(1 * B_ + b) * 8) * HW_ + r);
    const float4* p2 = (const float4*)(d_part + ((size_t)(2 * B_ + b) * 8) * HW_ + r);
    const float4* p3 = (const float4*)(d_part + ((size_t)(3 * B_ + b) * 8) * HW_ + r);
    float4 v0 = *p0, v1 = *p1, v2 = *p2, v3 = *p3;
    float bo = b_off[oc];
    float4 o;
    o.x = tanhf(v0.x + v1.x + v2.x + v3.x + bo);
    o.y = tanhf(v0.y + v1.y + v2.y + v3.y + bo);
    o.z = tanhf(v0.z + v1.z + v2.z + v3.z + bo);
    o.w = tanhf(v0.w + v1.w + v2.w + v3.w + bo);
    *(float4*)(d_off + (size_t)b * 8 * HW_ + r) = o;
}

// ---------------------------------------------------------------------------
// K3: offset upsample + grid_sample. Channel-pair packed smem tile;
//     16x32 output px per block. Segment launch: grid (32, G_, BH_).
// ---------------------------------------------------------------------------
#define K3TW 18
#define K3TH 10
#define K3P  181
__global__ __launch_bounds__(512) void k3_sample(float* __restrict__ out, int b0) {
    int bx = blockIdx.x;
    int ys0 = (bx >> 2) * 16;
    int xs0 = (bx & 3) * 32;
    int g = blockIdx.y;
    int b = b0 + blockIdx.z;
    int tid = threadIdx.x;
    int warp = tid >> 5;
    int lane = tid & 31;

    __shared__ float tile[16 * K3P * 2];
    __shared__ int   s_r[16][32][4];
    __shared__ float s_w[16][32][4];

    const float SY = 63.0f / 127.0f;
    const float SO = 63.0f / 128.0f;

    int x_lo = max(0, (int)floorf(xs0 * SY - 0.4923f));
    int y_lo = max(0, (int)floorf(ys0 * SY - 0.4923f));

    const float* pb = d_p + (size_t)(b * G_ + g) * HW_ * CG_;
    {
        uint32_t st0 = (uint32_t)__cvta_generic_to_shared(&tile[0]);
        for (int idx = tid; idx < K3TH * K3TW * CG_; idx += 512) {
            int p = idx >> 5;
            int c = idx & 31;
            int y = min(y_lo + p / K3TW, H_ - 1);
            int xx = min(x_lo + p % K3TW, W_ - 1);
            const float* src = &pb[(y * W_ + xx) * CG_ + c];
            uint32_t dst = st0 + (uint32_t)(((c & 15) * K3P + p) * 2 + (c >> 4)) * 4u;
            asm volatile("cp.async.ca.shared.global [%0], [%1], 4;"
                         :: "r"(dst), "l"(src));
        }
        asm volatile("cp.async.commit_group;");
    }

    {
        int r = tid >> 5;
        int xl = tid & 31;
        int ys = ys0 + r;
        int xs = xs0 + xl;

        float py = ys * SY;
        int y0u = (int)py;
        float wyu = py - y0u;
        int y1u = min(y0u + 1, H_ - 1);
        float px = xs * SY;
        int x0u = (int)px;
        float wxu = px - x0u;
        int x1u = min(x0u + 1, W_ - 1);

        const float* offx = d_off + (size_t)(b * 8 + 2 * g) * HW_;
        const float* offy = offx + HW_;

        float a00 = offx[y0u * W_ + x0u], a01 = offx[y0u * W_ + x1u];
        float a10 = offx[y1u * W_ + x0u], a11 = offx[y1u * W_ + x1u];
        float o_x = (a00 * (1.f - wxu) + a01 * wxu) * (1.f - wyu)
                  + (a10 * (1.f - wxu) + a11 * wxu) * wyu;

        float c00 = offy[y0u * W_ + x0u], c01 = offy[y0u * W_ + x1u];
        float c10 = offy[y1u * W_ + x0u], c11 = offy[y1u * W_ + x1u];
        float o_y = (c00 * (1.f - wxu) + c01 * wxu) * (1.f - wyu)
                  + (c10 * (1.f - wxu) + c11 * wxu) * wyu;

        float ix = fminf(fmaxf(px + o_x * SO, 0.f), (float)(W_ - 1));
        float iy = fminf(fmaxf(py + o_y * SO, 0.f), (float)(H_ - 1));

        int ix0 = (int)ix; if (ix0 > W_ - 1) ix0 = W_ - 1;
        int iy0 = (int)iy; if (iy0 > H_ - 1) iy0 = H_ - 1;
        int ix1 = min(ix0 + 1, W_ - 1);
        int iy1 = min(iy0 + 1, H_ - 1);
        float fx = ix - ix0;
        float fy = iy - iy0;

        int base = (iy0 - y_lo) * K3TW + (ix0 - x_lo);
        int dxo = ix1 - ix0;
        int dyo = (iy1 - iy0) * K3TW;
        s_r[r][xl][0] = base;
        s_r[r][xl][1] = base + dxo;
        s_r[r][xl][2] = base + dyo;
        s_r[r][xl][3] = base + dyo + dxo;
        s_w[r][xl][0] = (1.f - fx) * (1.f - fy);
        s_w[r][xl][1] = fx * (1.f - fy);
        s_w[r][xl][2] = (1.f - fx) * fy;
        s_w[r][xl][3] = fx * fy;
    }

    asm volatile("cp.async.wait_group 0;" ::: "memory");
    __syncthreads();

    const float2* tc = (const float2*)&tile[warp * K3P * 2];
    float* ob0 = out + ((size_t)(b * C_ + g * CG_ + warp) * HS_ + ys0) * WS_ + xs0 + lane;
    float* ob1 = ob0 + (size_t)16 * HS_ * WS_;
#pragma unroll
    for (int r = 0; r < 16; r++) {
        int4 rr = *(const int4*)&s_r[r][lane][0];
        float4 w = *(const float4*)&s_w[r][lane][0];
        float2 v00 = tc[rr.x];
        float2 v01 = tc[rr.y];
        float2 v10 = tc[rr.z];
        float2 v11 = tc[rr.w];
        float2 res = fma2(v00, make_float2(w.x, w.x),
                     fma2(v01, make_float2(w.y, w.y),
                     fma2(v10, make_float2(w.z, w.z),
                     mul2(v11, make_float2(w.w, w.w)))));
        ob0[(size_t)r * WS_] = res.x;
        ob1[(size_t)r * WS_] = res.y;
    }
}

// ---------------------------------------------------------------------------
// Launcher: 2-segment pipelined schedule (graph-capturable, small graph).
//   sB:   k0 -> k1(h0) -> k1(h1)            (evB[h] after each)
//   null: k2a(h0) -> k2b(h0) -> k2a(h1) -> k2b(h1)   (evA[h] after each k2b)
//   sC:   wait(evA[h], evB[h]) -> k3(h)
//   null joins on sC's last k3.
// ---------------------------------------------------------------------------
extern "C" void kernel_launch(void* const* d_in, const int* in_sizes, int n_in,
                              void* d_out, int out_size) {
    const float* x      = (const float*)d_in[0];
    const float* w_off  = (const float*)d_in[1];
    const float* b_off  = (const float*)d_in[2];
    const float* w_proj = (const float*)d_in[3];
    const float* gamma  = (const float*)d_in[4];
    const float* beta   = (const float*)d_in[5];
    const float* mean   = (const float*)d_in[6];
    const float* var    = (const float*)d_in[7];
    float* out = (float*)d_out;

    static cudaStream_t sB = nullptr, sC = nullptr;
    static cudaEvent_t evFork = nullptr, evDone = nullptr;
    static cudaEvent_t evA[2], evB[2];
    if (sB == nullptr) {
        cudaStreamCreateWithFlags(&sB, cudaStreamNonBlocking);
        cudaStreamCreateWithFlags(&sC, cudaStreamNonBlocking);
        cudaEventCreateWithFlags(&evFork, cudaEventDisableTiming);
        cudaEventCreateWithFlags(&evDone, cudaEventDisableTiming);
        for (int h = 0; h < 2; h++) {
            cudaEventCreateWithFlags(&evA[h], cudaEventDisableTiming);
            cudaEventCreateWithFlags(&evB[h], cudaEventDisableTiming);
        }
    }

    // fork from capture stream
    cudaEventRecord(evFork, 0);
    cudaStreamWaitEvent(sB, evFork, 0);

    // sB: weight prep once, then GEMM halves
    k0_prep<<<64, 256, 0, sB>>>(w_proj, gamma, beta, mean, var);

    const int n4h = (BH_ * 8 * HW_ / 4 + 255) / 256;
    for (int h = 0; h < 2; h++) {
        int b0 = h * BH_;

        // sB: projection GEMM for this half
        k1_mma<<<dim3(32, BH_), 256, 0, sB>>>(x, b0);
        cudaEventRecord(evB[h], sB);

        // null stream: offset conv + reduce for this half
        k2a_conv3<<<dim3(2, 4, BH_ * 4), dim3(16, 16)>>>(x, w_off, b0);
        k2b_reduce<<<n4h, 256>>>(b_off, b0);
        cudaEventRecord(evA[h], 0);

        // sC: sample this half once both producers are done
        cudaStreamWaitEvent(sC, evA[h], 0);
        cudaStreamWaitEvent(sC, evB[h], 0);
        k3_sample<<<dim3(32, G_, BH_), 512, 0, sC>>>(out, b0);
    }

    // join back to capture stream
    cudaEventRecord(evDone, sC);
    cudaStreamWaitEvent(0, evDone, 0);
}